// round 8
// baseline (speedup 1.0000x reference)
#include <cuda_runtime.h>
#include <cuda_bf16.h>
#include <cuda_fp16.h>
#include <math.h>
#include <cstdint>

#define HEADS 8
#define DIM 32
#define FEATS 256
#define NNODE_MAX 50000
#define NEDGE_MAX 800000
#define HSTR 272   // h row stride in halves: 256 h (512B) + 8 el fp32 (32B) = 544B, 16B-aligned

// ---------------- device scratch (no allocs allowed) ----------------
__device__ __half g_hh[(size_t)NNODE_MAX * HSTR];     // [row: 256 fp16 h | 8 fp32 el]
__device__ float g_elr[NNODE_MAX * 16];               // [node][8..15]=er (el lives in g_hh tail)
__device__ float g_lgs[(size_t)NEDGE_MAX * 8];        // ee-only pre-logits in CSR order
__device__ int   g_src_s[NEDGE_MAX];                  // src in CSR order
__device__ int   g_deg[NNODE_MAX];
__device__ int   g_off[NNODE_MAX + 1];
__device__ int   g_cursor[NNODE_MAX];
__device__ __nv_bfloat16 g_Bhi[FEATS * FEATS];        // W^T hi split, [n][k]
__device__ __nv_bfloat16 g_Blo[FEATS * FEATS];        // W^T lo split, [n][k]

// ---------------- 0) prep: W^T split into bf16 hi/lo ----------------
__global__ void prep_w_kernel(const float* __restrict__ W) {
    int k = blockIdx.x;          // 0..255
    int n = threadIdx.x;         // 0..255
    float v = W[k * FEATS + n];
    __nv_bfloat16 hi = __float2bfloat16(v);
    float lo = v - __bfloat162float(hi);
    g_Bhi[n * FEATS + k] = hi;
    g_Blo[n * FEATS + k] = __float2bfloat16(lo);
}

// ---------------- 1) bf16 split-3 HMMA GEMM: h = feat @ W, fused el/er ----------------
#define SSTR 72
#define SM_AH 0
#define SM_AL 18432
#define SM_BH 36864
#define SM_BL 73728
#define SM_GEMM_TOT 110592

__device__ __forceinline__ void mma16816(float* c, const uint32_t* a, const uint32_t* b) {
    asm volatile(
        "mma.sync.aligned.m16n8k16.row.col.f32.bf16.bf16.f32 "
        "{%0,%1,%2,%3}, {%4,%5,%6,%7}, {%8,%9}, {%0,%1,%2,%3};"
        : "+f"(c[0]), "+f"(c[1]), "+f"(c[2]), "+f"(c[3])
        : "r"(a[0]), "r"(a[1]), "r"(a[2]), "r"(a[3]), "r"(b[0]), "r"(b[1]));
}

__global__ __launch_bounds__(512) void gemm_mma_kernel(
    const float* __restrict__ A, const float* __restrict__ attn_l,
    const float* __restrict__ attn_r, int Mtot)
{
    extern __shared__ char sm[];
    __nv_bfloat16* sAh = (__nv_bfloat16*)(sm + SM_AH);
    __nv_bfloat16* sAl = (__nv_bfloat16*)(sm + SM_AL);
    __nv_bfloat16* sBh = (__nv_bfloat16*)(sm + SM_BH);
    __nv_bfloat16* sBl = (__nv_bfloat16*)(sm + SM_BL);

    int tid = threadIdx.x, wid = tid >> 5, lane = tid & 31;
    int m0 = blockIdx.x * 128;
    int mhalf = wid >> 3;
    int head  = wid & 7;
    int fr = lane >> 2;
    int fk = (lane & 3) * 2;

    float acc[4][4][4];
    #pragma unroll
    for (int i = 0; i < 4; i++)
        #pragma unroll
        for (int j = 0; j < 4; j++)
            #pragma unroll
            for (int c = 0; c < 4; c++) acc[i][j][c] = 0.f;

    for (int kc = 0; kc < 4; kc++) {
        #pragma unroll
        for (int g = tid; g < 2048; g += 512) {
            int row = g >> 4;
            int kq  = (g & 15) * 4;
            int grow = m0 + row;
            float4 v = make_float4(0.f, 0.f, 0.f, 0.f);
            if (grow < Mtot) v = *(const float4*)(A + (size_t)grow * FEATS + kc * 64 + kq);
            __nv_bfloat162 h01 = __floats2bfloat162_rn(v.x, v.y);
            __nv_bfloat162 h23 = __floats2bfloat162_rn(v.z, v.w);
            float lx = v.x - __bfloat162float(h01.x);
            float ly = v.y - __bfloat162float(h01.y);
            float lz = v.z - __bfloat162float(h23.x);
            float lw = v.w - __bfloat162float(h23.y);
            __nv_bfloat162 l01 = __floats2bfloat162_rn(lx, ly);
            __nv_bfloat162 l23 = __floats2bfloat162_rn(lz, lw);
            uint2 hp, lp;
            hp.x = reinterpret_cast<uint32_t&>(h01);
            hp.y = reinterpret_cast<uint32_t&>(h23);
            lp.x = reinterpret_cast<uint32_t&>(l01);
            lp.y = reinterpret_cast<uint32_t&>(l23);
            *(uint2*)(sAh + row * SSTR + kq) = hp;
            *(uint2*)(sAl + row * SSTR + kq) = lp;
        }
        #pragma unroll
        for (int g = tid; g < 2048; g += 512) {
            int n  = g >> 3;
            int kq = (g & 7) * 8;
            *(uint4*)(sBh + n * SSTR + kq) = *(const uint4*)(g_Bhi + n * FEATS + kc * 64 + kq);
            *(uint4*)(sBl + n * SSTR + kq) = *(const uint4*)(g_Blo + n * FEATS + kc * 64 + kq);
        }
        __syncthreads();

        #pragma unroll
        for (int ks = 0; ks < 4; ks++) {
            int kb = ks * 16;
            uint32_t bh[4][2], bl[4][2];
            #pragma unroll
            for (int nt = 0; nt < 4; nt++) {
                int nn = head * 32 + nt * 8 + fr;
                bh[nt][0] = *(const uint32_t*)(sBh + nn * SSTR + kb + fk);
                bh[nt][1] = *(const uint32_t*)(sBh + nn * SSTR + kb + fk + 8);
                bl[nt][0] = *(const uint32_t*)(sBl + nn * SSTR + kb + fk);
                bl[nt][1] = *(const uint32_t*)(sBl + nn * SSTR + kb + fk + 8);
            }
            #pragma unroll
            for (int mt = 0; mt < 4; mt++) {
                int r0 = mhalf * 64 + mt * 16 + fr;
                uint32_t ah[4], al[4];
                ah[0] = *(const uint32_t*)(sAh + r0 * SSTR + kb + fk);
                ah[1] = *(const uint32_t*)(sAh + (r0 + 8) * SSTR + kb + fk);
                ah[2] = *(const uint32_t*)(sAh + r0 * SSTR + kb + fk + 8);
                ah[3] = *(const uint32_t*)(sAh + (r0 + 8) * SSTR + kb + fk + 8);
                al[0] = *(const uint32_t*)(sAl + r0 * SSTR + kb + fk);
                al[1] = *(const uint32_t*)(sAl + (r0 + 8) * SSTR + kb + fk);
                al[2] = *(const uint32_t*)(sAl + r0 * SSTR + kb + fk + 8);
                al[3] = *(const uint32_t*)(sAl + (r0 + 8) * SSTR + kb + fk + 8);
                #pragma unroll
                for (int nt = 0; nt < 4; nt++) {
                    mma16816(acc[mt][nt], ah, bh[nt]);
                    mma16816(acc[mt][nt], ah, bl[nt]);
                    mma16816(acc[mt][nt], al, bh[nt]);
                }
            }
        }
        __syncthreads();
    }

    // --- epilogue: store h rows (fp16) + el (fp32, row tail) + er ---
    float2 alv[4], arv[4];
    #pragma unroll
    for (int nt = 0; nt < 4; nt++) {
        alv[nt] = *(const float2*)(attn_l + head * 32 + nt * 8 + fk);
        arv[nt] = *(const float2*)(attn_r + head * 32 + nt * 8 + fk);
    }
    #pragma unroll
    for (int mt = 0; mt < 4; mt++) {
        #pragma unroll
        for (int half = 0; half < 2; half++) {
            int row = m0 + mhalf * 64 + mt * 16 + fr + half * 8;
            int ci = half * 2;
            float el = 0.f, er = 0.f;
            if (row < Mtot) {
                __half* dp = g_hh + (size_t)row * HSTR + head * 32;
                #pragma unroll
                for (int nt = 0; nt < 4; nt++) {
                    float v0 = acc[mt][nt][ci], v1 = acc[mt][nt][ci + 1];
                    *(__half2*)(dp + nt * 8 + fk) = __floats2half2_rn(v0, v1);
                    el = fmaf(v0, alv[nt].x, fmaf(v1, alv[nt].y, el));
                    er = fmaf(v0, arv[nt].x, fmaf(v1, arv[nt].y, er));
                }
            }
            el += __shfl_xor_sync(~0u, el, 1);
            el += __shfl_xor_sync(~0u, el, 2);
            er += __shfl_xor_sync(~0u, er, 1);
            er += __shfl_xor_sync(~0u, er, 2);
            if ((lane & 3) == 0 && row < Mtot) {
                ((float*)(g_hh + (size_t)row * HSTR + 256))[head] = el;  // row tail
                g_elr[row * 16 + 8 + head] = er;
            }
        }
    }
}

// ---------------- 2) zero degree ----------------
__global__ void zero_deg_kernel(int N) {
    int i = blockIdx.x * blockDim.x + threadIdx.x;
    if (i < N) g_deg[i] = 0;
}

// ---------------- 3) dst histogram ----------------
__global__ __launch_bounds__(256) void hist_kernel(const int* __restrict__ dst, int E) {
    int e = blockIdx.x * blockDim.x + threadIdx.x;
    if (e < E) atomicAdd(&g_deg[dst[e]], 1);
}

// ---------------- 4) single-block scan: deg -> off, cursor ----------------
__global__ __launch_bounds__(1024) void scan_kernel(int N) {
    __shared__ int wsum[32];
    __shared__ int s_carry;
    int tid = threadIdx.x, lane = tid & 31, w = tid >> 5;
    if (tid == 0) { s_carry = 0; g_off[0] = 0; }
    __syncthreads();

    for (int base = 0; base < N; base += 4096) {
        int i0 = base + tid * 4;
        int4 x = make_int4(0, 0, 0, 0);
        if (i0 + 3 < N) {
            x = *(const int4*)(g_deg + i0);
        } else {
            if (i0 < N)     x.x = g_deg[i0];
            if (i0 + 1 < N) x.y = g_deg[i0 + 1];
            if (i0 + 2 < N) x.z = g_deg[i0 + 2];
            if (i0 + 3 < N) x.w = g_deg[i0 + 3];
        }
        int p1 = x.x, p2 = p1 + x.y, p3 = p2 + x.z, p4 = p3 + x.w;
        int v = p4;
        #pragma unroll
        for (int o = 1; o < 32; o <<= 1) {
            int t = __shfl_up_sync(~0u, v, o);
            if (lane >= o) v += t;
        }
        if (lane == 31) wsum[w] = v;
        __syncthreads();
        if (w == 0) {
            int t = wsum[lane];
            #pragma unroll
            for (int o = 1; o < 32; o <<= 1) {
                int u = __shfl_up_sync(~0u, t, o);
                if (lane >= o) t += u;
            }
            wsum[lane] = t;
        }
        __syncthreads();
        int carry = s_carry;
        int base_t = carry + (w ? wsum[w - 1] : 0) + (v - p4);
        if (i0 < N)     { g_cursor[i0]     = base_t;      g_off[i0 + 1] = base_t + p1; }
        if (i0 + 1 < N) { g_cursor[i0 + 1] = base_t + p1; g_off[i0 + 2] = base_t + p2; }
        if (i0 + 2 < N) { g_cursor[i0 + 2] = base_t + p2; g_off[i0 + 3] = base_t + p3; }
        if (i0 + 3 < N) { g_cursor[i0 + 3] = base_t + p3; g_off[i0 + 4] = base_t + p4; }
        __syncthreads();
        if (tid == 0) s_carry = carry + wsum[31];
        __syncthreads();
    }
}

// ---------------- 5) ee-only pre-logits + CSR scatter (GEMM-INDEPENDENT) ----------------
__global__ __launch_bounds__(256) void edge_kernel(
    const float* __restrict__ edge_emb, const int* __restrict__ src,
    const int* __restrict__ dst, const float* __restrict__ W_e,
    const float* __restrict__ attn_e, int E)
{
    __shared__ float Msh[8][8];
    int tid = threadIdx.x;
    if (tid < 64) {
        int k = tid >> 3, hh = tid & 7;
        float s = 0.f;
        #pragma unroll
        for (int d = 0; d < DIM; d++)
            s += W_e[k * FEATS + hh * DIM + d] * attn_e[hh * DIM + d];
        Msh[k][hh] = s;
    }
    __syncthreads();

    int e0 = (blockIdx.x * 256 + tid) * 4;
    if (e0 >= E) return;
    int elim = min(e0 + 4, E);

    for (int e = e0; e < elim; e++) {
        int s_ = src[e], d_ = dst[e];
        float4 a0 = *(const float4*)(edge_emb + (size_t)e * 8);
        float4 a1 = *(const float4*)(edge_emb + (size_t)e * 8 + 4);
        float emb[8] = {a0.x, a0.y, a0.z, a0.w, a1.x, a1.y, a1.z, a1.w};
        float lg[8];
        #pragma unroll
        for (int hh = 0; hh < 8; hh++) {
            float ee = 0.f;
            #pragma unroll
            for (int k = 0; k < 8; k++) ee = fmaf(emb[k], Msh[k][hh], ee);
            lg[hh] = ee;                       // ee only; el/er added in agg
        }
        int pos = atomicAdd(&g_cursor[d_], 1);
        g_src_s[pos] = s_;
        *(float4*)(g_lgs + (size_t)pos * 8)     = make_float4(lg[0], lg[1], lg[2], lg[3]);
        *(float4*)(g_lgs + (size_t)pos * 8 + 4) = make_float4(lg[4], lg[5], lg[6], lg[7]);
    }
}

// ---------------- 6) single-pass softmax + aggregation (el from h-row tail) ----------------
__global__ __launch_bounds__(256) void agg_kernel(
    const float* __restrict__ bias, float* __restrict__ out, int N)
{
    int warp = (blockIdx.x * blockDim.x + threadIdx.x) >> 5;
    int lane = threadIdx.x & 31;
    if (warp >= N) return;
    int beg = g_off[warp], end = g_off[warp + 1];

    int hh2 = lane >> 2;
    int col = lane * 8;
    float er2 = g_elr[warp * 16 + 8 + hh2];

    float S = 0.f;
    float4 acc0 = make_float4(0.f, 0.f, 0.f, 0.f);
    float4 acc1 = make_float4(0.f, 0.f, 0.f, 0.f);

    int j = beg;
    for (; j + 3 < end; j += 4) {
        int s[4];
        #pragma unroll
        for (int q = 0; q < 4; q++) s[q] = g_src_s[j + q];
        float xr[4];
        #pragma unroll
        for (int q = 0; q < 4; q++) xr[q] = g_lgs[(size_t)(j + q) * 8 + hh2];
        uint4 hq[4];
        float elq[4];
        #pragma unroll
        for (int q = 0; q < 4; q++) {
            const __half* rb = g_hh + (size_t)s[q] * HSTR;
            hq[q]  = *(const uint4*)(rb + col);
            elq[q] = ((const float*)(rb + 256))[hh2];
        }
        #pragma unroll
        for (int q = 0; q < 4; q++) {
            float x = xr[q] + elq[q] + er2;
            x = x >= 0.f ? x : 0.2f * x;
            float w = __expf(x);
            S += w;
            float2 f0 = __half22float2(*reinterpret_cast<__half2*>(&hq[q].x));
            float2 f1 = __half22float2(*reinterpret_cast<__half2*>(&hq[q].y));
            float2 f2 = __half22float2(*reinterpret_cast<__half2*>(&hq[q].z));
            float2 f3 = __half22float2(*reinterpret_cast<__half2*>(&hq[q].w));
            acc0.x = fmaf(w, f0.x, acc0.x);
            acc0.y = fmaf(w, f0.y, acc0.y);
            acc0.z = fmaf(w, f1.x, acc0.z);
            acc0.w = fmaf(w, f1.y, acc0.w);
            acc1.x = fmaf(w, f2.x, acc1.x);
            acc1.y = fmaf(w, f2.y, acc1.y);
            acc1.z = fmaf(w, f3.x, acc1.z);
            acc1.w = fmaf(w, f3.y, acc1.w);
        }
    }
    for (; j < end; j++) {
        int sidx = g_src_s[j];
        const __half* rb = g_hh + (size_t)sidx * HSTR;
        float x = g_lgs[(size_t)j * 8 + hh2] + ((const float*)(rb + 256))[hh2] + er2;
        x = x >= 0.f ? x : 0.2f * x;
        float w = __expf(x);
        S += w;
        uint4 q = *(const uint4*)(rb + col);
        float2 f0 = __half22float2(*reinterpret_cast<__half2*>(&q.x));
        float2 f1 = __half22float2(*reinterpret_cast<__half2*>(&q.y));
        float2 f2 = __half22float2(*reinterpret_cast<__half2*>(&q.z));
        float2 f3 = __half22float2(*reinterpret_cast<__half2*>(&q.w));
        acc0.x = fmaf(w, f0.x, acc0.x);
        acc0.y = fmaf(w, f0.y, acc0.y);
        acc0.z = fmaf(w, f1.x, acc0.z);
        acc0.w = fmaf(w, f1.y, acc0.w);
        acc1.x = fmaf(w, f2.x, acc1.x);
        acc1.y = fmaf(w, f2.y, acc1.y);
        acc1.z = fmaf(w, f3.x, acc1.z);
        acc1.w = fmaf(w, f3.y, acc1.w);
    }

    float inv = 1.0f / (S + 1e-9f);
    const float4* bp = (const float4*)(bias + col);
    float4 b0 = bp[0], b1 = bp[1];
    float4* op = (float4*)(out + (size_t)warp * FEATS + col);
    op[0] = make_float4(fmaf(acc0.x, inv, b0.x), fmaf(acc0.y, inv, b0.y),
                        fmaf(acc0.z, inv, b0.z), fmaf(acc0.w, inv, b0.w));
    op[1] = make_float4(fmaf(acc1.x, inv, b1.x), fmaf(acc1.y, inv, b1.y),
                        fmaf(acc1.z, inv, b1.z), fmaf(acc1.w, inv, b1.w));
}

// ---------------- launch: 2-branch DAG; edge now fully overlapped with GEMM ----------------
extern "C" void kernel_launch(void* const* d_in, const int* in_sizes, int n_in,
                              void* d_out, int out_size)
{
    const float* feat     = (const float*)d_in[0];
    const float* edge_emb = (const float*)d_in[1];
    const int*   src      = (const int*)d_in[2];
    const int*   dst      = (const int*)d_in[3];
    const float* W_src    = (const float*)d_in[4];
    const float* W_e      = (const float*)d_in[5];
    const float* attn_l   = (const float*)d_in[6];
    const float* attn_r   = (const float*)d_in[7];
    const float* attn_e   = (const float*)d_in[8];
    const float* bias     = (const float*)d_in[9];
    float* out = (float*)d_out;

    int N = in_sizes[0] / FEATS;   // 50000
    int E = in_sizes[2];           // 800000

    cudaFuncSetAttribute(gemm_mma_kernel,
                         cudaFuncAttributeMaxDynamicSharedMemorySize, SM_GEMM_TOT);

    // Side stream for the entire edge pipeline (independent of GEMM chain).
    // Streams/events intentionally not destroyed during capture (bounded host leak).
    cudaStream_t s2;
    cudaStreamCreateWithFlags(&s2, cudaStreamNonBlocking);
    cudaEvent_t evFork, evJoin;
    cudaEventCreateWithFlags(&evFork, cudaEventDisableTiming);
    cudaEventCreateWithFlags(&evJoin, cudaEventDisableTiming);

    cudaEventRecord(evFork, 0);
    cudaStreamWaitEvent(s2, evFork, 0);

    // main stream: W prep + GEMM (+fused el/er)
    prep_w_kernel<<<FEATS, FEATS>>>(W_src);
    int gtiles = (N + 127) / 128;
    gemm_mma_kernel<<<gtiles, 512, SM_GEMM_TOT>>>(feat, attn_l, attn_r, N);

    // side stream: CSR build + ee pre-logits (no GEMM dependency)
    zero_deg_kernel<<<(N + 255) / 256, 256, 0, s2>>>(N);
    hist_kernel<<<(E + 255) / 256, 256, 0, s2>>>(dst, E);
    scan_kernel<<<1, 1024, 0, s2>>>(N);
    edge_kernel<<<((E + 3) / 4 + 255) / 256, 256, 0, s2>>>(edge_emb, src, dst, W_e, attn_e, E);

    cudaEventRecord(evJoin, s2);
    cudaStreamWaitEvent(0, evJoin, 0);

    // join: aggregate (needs h+el from GEMM and CSR from side stream)
    agg_kernel<<<((N * 32) + 255) / 256, 256>>>(bias, out, N);
}

// round 9
// speedup vs baseline: 1.1324x; 1.1324x over previous
#include <cuda_runtime.h>
#include <cuda_bf16.h>
#include <cuda_fp16.h>
#include <math.h>
#include <cstdint>

#define HEADS 8
#define DIM 32
#define FEATS 256
#define NNODE_MAX 50000
#define NEDGE_MAX 800000

// ---------------- device scratch (no allocs allowed) ----------------
__device__ __half g_hh[(size_t)NNODE_MAX * FEATS];    // projected node features (fp16, 512B-aligned rows)
__device__ float g_elr[NNODE_MAX * 16];               // [node][0..7]=el, [8..15]=er
__device__ float g_lgs[(size_t)NEDGE_MAX * 8];        // ee-only pre-logits in CSR order
__device__ int   g_src_s[NEDGE_MAX];                  // src in CSR order
__device__ int   g_deg[NNODE_MAX];
__device__ int   g_off[NNODE_MAX + 1];
__device__ int   g_cursor[NNODE_MAX];
__device__ __nv_bfloat16 g_Bhi[FEATS * FEATS];        // W^T hi split, [n][k]
__device__ __nv_bfloat16 g_Blo[FEATS * FEATS];        // W^T lo split, [n][k]

// ---------------- 0) prep: W^T split into bf16 hi/lo ----------------
__global__ void prep_w_kernel(const float* __restrict__ W) {
    int k = blockIdx.x;          // 0..255
    int n = threadIdx.x;         // 0..255
    float v = W[k * FEATS + n];
    __nv_bfloat16 hi = __float2bfloat16(v);
    float lo = v - __bfloat162float(hi);
    g_Bhi[n * FEATS + k] = hi;
    g_Blo[n * FEATS + k] = __float2bfloat16(lo);
}

// ---------------- 1) bf16 split-3 HMMA GEMM: h = feat @ W, fused el/er ----------------
#define SSTR 72
#define SM_AH 0
#define SM_AL 18432
#define SM_BH 36864
#define SM_BL 73728
#define SM_GEMM_TOT 110592

__device__ __forceinline__ void mma16816(float* c, const uint32_t* a, const uint32_t* b) {
    asm volatile(
        "mma.sync.aligned.m16n8k16.row.col.f32.bf16.bf16.f32 "
        "{%0,%1,%2,%3}, {%4,%5,%6,%7}, {%8,%9}, {%0,%1,%2,%3};"
        : "+f"(c[0]), "+f"(c[1]), "+f"(c[2]), "+f"(c[3])
        : "r"(a[0]), "r"(a[1]), "r"(a[2]), "r"(a[3]), "r"(b[0]), "r"(b[1]));
}

__global__ __launch_bounds__(512) void gemm_mma_kernel(
    const float* __restrict__ A, const float* __restrict__ attn_l,
    const float* __restrict__ attn_r, int Mtot)
{
    extern __shared__ char sm[];
    __nv_bfloat16* sAh = (__nv_bfloat16*)(sm + SM_AH);
    __nv_bfloat16* sAl = (__nv_bfloat16*)(sm + SM_AL);
    __nv_bfloat16* sBh = (__nv_bfloat16*)(sm + SM_BH);
    __nv_bfloat16* sBl = (__nv_bfloat16*)(sm + SM_BL);

    int tid = threadIdx.x, wid = tid >> 5, lane = tid & 31;
    int m0 = blockIdx.x * 128;
    int mhalf = wid >> 3;
    int head  = wid & 7;
    int fr = lane >> 2;
    int fk = (lane & 3) * 2;

    float acc[4][4][4];
    #pragma unroll
    for (int i = 0; i < 4; i++)
        #pragma unroll
        for (int j = 0; j < 4; j++)
            #pragma unroll
            for (int c = 0; c < 4; c++) acc[i][j][c] = 0.f;

    for (int kc = 0; kc < 4; kc++) {
        #pragma unroll
        for (int g = tid; g < 2048; g += 512) {
            int row = g >> 4;
            int kq  = (g & 15) * 4;
            int grow = m0 + row;
            float4 v = make_float4(0.f, 0.f, 0.f, 0.f);
            if (grow < Mtot) v = *(const float4*)(A + (size_t)grow * FEATS + kc * 64 + kq);
            __nv_bfloat162 h01 = __floats2bfloat162_rn(v.x, v.y);
            __nv_bfloat162 h23 = __floats2bfloat162_rn(v.z, v.w);
            float lx = v.x - __bfloat162float(h01.x);
            float ly = v.y - __bfloat162float(h01.y);
            float lz = v.z - __bfloat162float(h23.x);
            float lw = v.w - __bfloat162float(h23.y);
            __nv_bfloat162 l01 = __floats2bfloat162_rn(lx, ly);
            __nv_bfloat162 l23 = __floats2bfloat162_rn(lz, lw);
            uint2 hp, lp;
            hp.x = reinterpret_cast<uint32_t&>(h01);
            hp.y = reinterpret_cast<uint32_t&>(h23);
            lp.x = reinterpret_cast<uint32_t&>(l01);
            lp.y = reinterpret_cast<uint32_t&>(l23);
            *(uint2*)(sAh + row * SSTR + kq) = hp;
            *(uint2*)(sAl + row * SSTR + kq) = lp;
        }
        #pragma unroll
        for (int g = tid; g < 2048; g += 512) {
            int n  = g >> 3;
            int kq = (g & 7) * 8;
            *(uint4*)(sBh + n * SSTR + kq) = *(const uint4*)(g_Bhi + n * FEATS + kc * 64 + kq);
            *(uint4*)(sBl + n * SSTR + kq) = *(const uint4*)(g_Blo + n * FEATS + kc * 64 + kq);
        }
        __syncthreads();

        #pragma unroll
        for (int ks = 0; ks < 4; ks++) {
            int kb = ks * 16;
            uint32_t bh[4][2], bl[4][2];
            #pragma unroll
            for (int nt = 0; nt < 4; nt++) {
                int nn = head * 32 + nt * 8 + fr;
                bh[nt][0] = *(const uint32_t*)(sBh + nn * SSTR + kb + fk);
                bh[nt][1] = *(const uint32_t*)(sBh + nn * SSTR + kb + fk + 8);
                bl[nt][0] = *(const uint32_t*)(sBl + nn * SSTR + kb + fk);
                bl[nt][1] = *(const uint32_t*)(sBl + nn * SSTR + kb + fk + 8);
            }
            #pragma unroll
            for (int mt = 0; mt < 4; mt++) {
                int r0 = mhalf * 64 + mt * 16 + fr;
                uint32_t ah[4], al[4];
                ah[0] = *(const uint32_t*)(sAh + r0 * SSTR + kb + fk);
                ah[1] = *(const uint32_t*)(sAh + (r0 + 8) * SSTR + kb + fk);
                ah[2] = *(const uint32_t*)(sAh + r0 * SSTR + kb + fk + 8);
                ah[3] = *(const uint32_t*)(sAh + (r0 + 8) * SSTR + kb + fk + 8);
                al[0] = *(const uint32_t*)(sAl + r0 * SSTR + kb + fk);
                al[1] = *(const uint32_t*)(sAl + (r0 + 8) * SSTR + kb + fk);
                al[2] = *(const uint32_t*)(sAl + r0 * SSTR + kb + fk + 8);
                al[3] = *(const uint32_t*)(sAl + (r0 + 8) * SSTR + kb + fk + 8);
                #pragma unroll
                for (int nt = 0; nt < 4; nt++) {
                    mma16816(acc[mt][nt], ah, bh[nt]);
                    mma16816(acc[mt][nt], ah, bl[nt]);
                    mma16816(acc[mt][nt], al, bh[nt]);
                }
            }
        }
        __syncthreads();
    }

    // --- epilogue: store h rows (fp16) + el/er (fp32, g_elr) ---
    float2 alv[4], arv[4];
    #pragma unroll
    for (int nt = 0; nt < 4; nt++) {
        alv[nt] = *(const float2*)(attn_l + head * 32 + nt * 8 + fk);
        arv[nt] = *(const float2*)(attn_r + head * 32 + nt * 8 + fk);
    }
    #pragma unroll
    for (int mt = 0; mt < 4; mt++) {
        #pragma unroll
        for (int half = 0; half < 2; half++) {
            int row = m0 + mhalf * 64 + mt * 16 + fr + half * 8;
            int ci = half * 2;
            float el = 0.f, er = 0.f;
            if (row < Mtot) {
                __half* dp = g_hh + (size_t)row * FEATS + head * 32;
                #pragma unroll
                for (int nt = 0; nt < 4; nt++) {
                    float v0 = acc[mt][nt][ci], v1 = acc[mt][nt][ci + 1];
                    *(__half2*)(dp + nt * 8 + fk) = __floats2half2_rn(v0, v1);
                    el = fmaf(v0, alv[nt].x, fmaf(v1, alv[nt].y, el));
                    er = fmaf(v0, arv[nt].x, fmaf(v1, arv[nt].y, er));
                }
            }
            el += __shfl_xor_sync(~0u, el, 1);
            el += __shfl_xor_sync(~0u, el, 2);
            er += __shfl_xor_sync(~0u, er, 1);
            er += __shfl_xor_sync(~0u, er, 2);
            if ((lane & 3) == 0 && row < Mtot) {
                g_elr[row * 16 + head] = el;
                g_elr[row * 16 + 8 + head] = er;
            }
        }
    }
}

// ---------------- 2) zero degree ----------------
__global__ void zero_deg_kernel(int N) {
    int i = blockIdx.x * blockDim.x + threadIdx.x;
    if (i < N) g_deg[i] = 0;
}

// ---------------- 3) dst histogram ----------------
__global__ __launch_bounds__(256) void hist_kernel(const int* __restrict__ dst, int E) {
    int e = blockIdx.x * blockDim.x + threadIdx.x;
    if (e < E) atomicAdd(&g_deg[dst[e]], 1);
}

// ---------------- 4) single-block scan: deg -> off, cursor ----------------
__global__ __launch_bounds__(1024) void scan_kernel(int N) {
    __shared__ int wsum[32];
    __shared__ int s_carry;
    int tid = threadIdx.x, lane = tid & 31, w = tid >> 5;
    if (tid == 0) { s_carry = 0; g_off[0] = 0; }
    __syncthreads();

    for (int base = 0; base < N; base += 4096) {
        int i0 = base + tid * 4;
        int4 x = make_int4(0, 0, 0, 0);
        if (i0 + 3 < N) {
            x = *(const int4*)(g_deg + i0);
        } else {
            if (i0 < N)     x.x = g_deg[i0];
            if (i0 + 1 < N) x.y = g_deg[i0 + 1];
            if (i0 + 2 < N) x.z = g_deg[i0 + 2];
            if (i0 + 3 < N) x.w = g_deg[i0 + 3];
        }
        int p1 = x.x, p2 = p1 + x.y, p3 = p2 + x.z, p4 = p3 + x.w;
        int v = p4;
        #pragma unroll
        for (int o = 1; o < 32; o <<= 1) {
            int t = __shfl_up_sync(~0u, v, o);
            if (lane >= o) v += t;
        }
        if (lane == 31) wsum[w] = v;
        __syncthreads();
        if (w == 0) {
            int t = wsum[lane];
            #pragma unroll
            for (int o = 1; o < 32; o <<= 1) {
                int u = __shfl_up_sync(~0u, t, o);
                if (lane >= o) t += u;
            }
            wsum[lane] = t;
        }
        __syncthreads();
        int carry = s_carry;
        int base_t = carry + (w ? wsum[w - 1] : 0) + (v - p4);
        if (i0 < N)     { g_cursor[i0]     = base_t;      g_off[i0 + 1] = base_t + p1; }
        if (i0 + 1 < N) { g_cursor[i0 + 1] = base_t + p1; g_off[i0 + 2] = base_t + p2; }
        if (i0 + 2 < N) { g_cursor[i0 + 2] = base_t + p2; g_off[i0 + 3] = base_t + p3; }
        if (i0 + 3 < N) { g_cursor[i0 + 3] = base_t + p3; g_off[i0 + 4] = base_t + p4; }
        __syncthreads();
        if (tid == 0) s_carry = carry + wsum[31];
        __syncthreads();
    }
}

// ---------------- 5) ee-only pre-logits + CSR scatter (GEMM-INDEPENDENT, streaming) ----------------
__global__ __launch_bounds__(256) void edge_kernel(
    const float* __restrict__ edge_emb, const int* __restrict__ src,
    const int* __restrict__ dst, const float* __restrict__ W_e,
    const float* __restrict__ attn_e, int E)
{
    __shared__ float Msh[8][8];
    int tid = threadIdx.x;
    if (tid < 64) {
        int k = tid >> 3, hh = tid & 7;
        float s = 0.f;
        #pragma unroll
        for (int d = 0; d < DIM; d++)
            s += W_e[k * FEATS + hh * DIM + d] * attn_e[hh * DIM + d];
        Msh[k][hh] = s;
    }
    __syncthreads();

    int e0 = (blockIdx.x * 256 + tid) * 4;
    if (e0 >= E) return;
    int elim = min(e0 + 4, E);

    for (int e = e0; e < elim; e++) {
        int s_ = src[e], d_ = dst[e];
        float4 a0 = *(const float4*)(edge_emb + (size_t)e * 8);
        float4 a1 = *(const float4*)(edge_emb + (size_t)e * 8 + 4);
        float emb[8] = {a0.x, a0.y, a0.z, a0.w, a1.x, a1.y, a1.z, a1.w};
        float lg[8];
        #pragma unroll
        for (int hh = 0; hh < 8; hh++) {
            float ee = 0.f;
            #pragma unroll
            for (int k = 0; k < 8; k++) ee = fmaf(emb[k], Msh[k][hh], ee);
            lg[hh] = ee;                       // ee only; el/er added in agg
        }
        int pos = atomicAdd(&g_cursor[d_], 1);
        g_src_s[pos] = s_;
        *(float4*)(g_lgs + (size_t)pos * 8)     = make_float4(lg[0], lg[1], lg[2], lg[3]);
        *(float4*)(g_lgs + (size_t)pos * 8 + 4) = make_float4(lg[4], lg[5], lg[6], lg[7]);
    }
}

// ---------------- 6) single-pass softmax + aggregation (el gathered from g_elr) ----------------
__global__ __launch_bounds__(256) void agg_kernel(
    const float* __restrict__ bias, float* __restrict__ out, int N)
{
    int warp = (blockIdx.x * blockDim.x + threadIdx.x) >> 5;
    int lane = threadIdx.x & 31;
    if (warp >= N) return;
    int beg = g_off[warp], end = g_off[warp + 1];

    int hh2 = lane >> 2;
    int col = lane * 8;
    float er2 = g_elr[warp * 16 + 8 + hh2];

    float S = 0.f;
    float4 acc0 = make_float4(0.f, 0.f, 0.f, 0.f);
    float4 acc1 = make_float4(0.f, 0.f, 0.f, 0.f);

    int j = beg;
    for (; j + 3 < end; j += 4) {
        int s[4];
        #pragma unroll
        for (int q = 0; q < 4; q++) s[q] = g_src_s[j + q];
        float xr[4];
        #pragma unroll
        for (int q = 0; q < 4; q++) xr[q] = g_lgs[(size_t)(j + q) * 8 + hh2];
        float elq[4];
        #pragma unroll
        for (int q = 0; q < 4; q++) elq[q] = g_elr[(size_t)s[q] * 16 + hh2];
        uint4 hq[4];
        #pragma unroll
        for (int q = 0; q < 4; q++)
            hq[q] = *(const uint4*)(g_hh + (size_t)s[q] * FEATS + col);

        #pragma unroll
        for (int q = 0; q < 4; q++) {
            float x = xr[q] + elq[q] + er2;
            x = x >= 0.f ? x : 0.2f * x;
            float w = __expf(x);
            S += w;
            float2 f0 = __half22float2(*reinterpret_cast<__half2*>(&hq[q].x));
            float2 f1 = __half22float2(*reinterpret_cast<__half2*>(&hq[q].y));
            float2 f2 = __half22float2(*reinterpret_cast<__half2*>(&hq[q].z));
            float2 f3 = __half22float2(*reinterpret_cast<__half2*>(&hq[q].w));
            acc0.x = fmaf(w, f0.x, acc0.x);
            acc0.y = fmaf(w, f0.y, acc0.y);
            acc0.z = fmaf(w, f1.x, acc0.z);
            acc0.w = fmaf(w, f1.y, acc0.w);
            acc1.x = fmaf(w, f2.x, acc1.x);
            acc1.y = fmaf(w, f2.y, acc1.y);
            acc1.z = fmaf(w, f3.x, acc1.z);
            acc1.w = fmaf(w, f3.y, acc1.w);
        }
    }
    for (; j < end; j++) {
        int sidx = g_src_s[j];
        float x = g_lgs[(size_t)j * 8 + hh2] + g_elr[(size_t)sidx * 16 + hh2] + er2;
        x = x >= 0.f ? x : 0.2f * x;
        float w = __expf(x);
        S += w;
        uint4 q = *(const uint4*)(g_hh + (size_t)sidx * FEATS + col);
        float2 f0 = __half22float2(*reinterpret_cast<__half2*>(&q.x));
        float2 f1 = __half22float2(*reinterpret_cast<__half2*>(&q.y));
        float2 f2 = __half22float2(*reinterpret_cast<__half2*>(&q.z));
        float2 f3 = __half22float2(*reinterpret_cast<__half2*>(&q.w));
        acc0.x = fmaf(w, f0.x, acc0.x);
        acc0.y = fmaf(w, f0.y, acc0.y);
        acc0.z = fmaf(w, f1.x, acc0.z);
        acc0.w = fmaf(w, f1.y, acc0.w);
        acc1.x = fmaf(w, f2.x, acc1.x);
        acc1.y = fmaf(w, f2.y, acc1.y);
        acc1.z = fmaf(w, f3.x, acc1.z);
        acc1.w = fmaf(w, f3.y, acc1.w);
    }

    float inv = 1.0f / (S + 1e-9f);
    const float4* bp = (const float4*)(bias + col);
    float4 b0 = bp[0], b1 = bp[1];
    float4* op = (float4*)(out + (size_t)warp * FEATS + col);
    op[0] = make_float4(fmaf(acc0.x, inv, b0.x), fmaf(acc0.y, inv, b0.y),
                        fmaf(acc0.z, inv, b0.z), fmaf(acc0.w, inv, b0.w));
    op[1] = make_float4(fmaf(acc1.x, inv, b1.x), fmaf(acc1.y, inv, b1.y),
                        fmaf(acc1.z, inv, b1.z), fmaf(acc1.w, inv, b1.w));
}

// ---------------- launch: 2-branch DAG; gemm as 4th launch for ncu capture ----------------
extern "C" void kernel_launch(void* const* d_in, const int* in_sizes, int n_in,
                              void* d_out, int out_size)
{
    const float* feat     = (const float*)d_in[0];
    const float* edge_emb = (const float*)d_in[1];
    const int*   src      = (const int*)d_in[2];
    const int*   dst      = (const int*)d_in[3];
    const float* W_src    = (const float*)d_in[4];
    const float* W_e      = (const float*)d_in[5];
    const float* attn_l   = (const float*)d_in[6];
    const float* attn_r   = (const float*)d_in[7];
    const float* attn_e   = (const float*)d_in[8];
    const float* bias     = (const float*)d_in[9];
    float* out = (float*)d_out;

    int N = in_sizes[0] / FEATS;   // 50000
    int E = in_sizes[2];           // 800000

    cudaFuncSetAttribute(gemm_mma_kernel,
                         cudaFuncAttributeMaxDynamicSharedMemorySize, SM_GEMM_TOT);

    // Side stream for CSR build + ee pre-logits (independent of GEMM chain).
    // Streams/events intentionally not destroyed during capture (bounded host leak).
    cudaStream_t s2;
    cudaStreamCreateWithFlags(&s2, cudaStreamNonBlocking);
    cudaEvent_t evFork, evJoin;
    cudaEventCreateWithFlags(&evFork, cudaEventDisableTiming);
    cudaEventCreateWithFlags(&evJoin, cudaEventDisableTiming);

    cudaEventRecord(evFork, 0);
    cudaStreamWaitEvent(s2, evFork, 0);

    // submission order matters only for ncu capture slot (4th launch = gemm):
    zero_deg_kernel<<<(N + 255) / 256, 256, 0, s2>>>(N);                 // 1
    hist_kernel<<<(E + 255) / 256, 256, 0, s2>>>(dst, E);                // 2
    prep_w_kernel<<<FEATS, FEATS>>>(W_src);                              // 3 (main)
    int gtiles = (N + 127) / 128;
    gemm_mma_kernel<<<gtiles, 512, SM_GEMM_TOT>>>(feat, attn_l, attn_r, N); // 4 (main) <- ncu
    scan_kernel<<<1, 1024, 0, s2>>>(N);                                  // 5
    edge_kernel<<<((E + 3) / 4 + 255) / 256, 256, 0, s2>>>(edge_emb, src, dst, W_e, attn_e, E); // 6

    cudaEventRecord(evJoin, s2);
    cudaStreamWaitEvent(0, evJoin, 0);

    // join: aggregate (needs h/el/er from GEMM and CSR+lgs from side stream)
    agg_kernel<<<((N * 32) + 255) / 256, 256>>>(bias, out, N);           // 7
}

// round 13
// speedup vs baseline: 1.1871x; 1.0484x over previous
#include <cuda_runtime.h>
#include <cuda_bf16.h>
#include <cuda_fp16.h>
#include <math.h>
#include <cstdint>

#define HEADS 8
#define DIM 32
#define FEATS 256
#define NNODE_MAX 50000
#define NEDGE_MAX 800000

// ---------------- device scratch (no allocs allowed) ----------------
__device__ __half g_hh[(size_t)NNODE_MAX * FEATS];    // projected node features (fp16, 512B rows)
__device__ float g_elr[NNODE_MAX * 16];               // [node][0..7]=el, [8..15]=er
__device__ float g_lgs[(size_t)NEDGE_MAX * 8];        // ee-only pre-logits in CSR order
__device__ int   g_src_s[NEDGE_MAX];                  // src in CSR order
__device__ int   g_deg[NNODE_MAX];
__device__ int   g_off[NNODE_MAX + 1];
__device__ int   g_cursor[NNODE_MAX];
__device__ __nv_bfloat16 g_Bhi[FEATS * FEATS];        // W^T hi split, [n][k]
__device__ __nv_bfloat16 g_Blo[FEATS * FEATS];        // W^T lo split, [n][k]

// ---------------- 0) prep: W^T split into bf16 hi/lo ----------------
__global__ void prep_w_kernel(const float* __restrict__ W) {
    int k = blockIdx.x;          // 0..255
    int n = threadIdx.x;         // 0..255
    float v = W[k * FEATS + n];
    __nv_bfloat16 hi = __float2bfloat16(v);
    float lo = v - __bfloat162float(hi);
    g_Bhi[n * FEATS + k] = hi;
    g_Blo[n * FEATS + k] = __float2bfloat16(lo);
}

// ---------------- 1) bf16 split-3 HMMA GEMM, M64xN256 tiles, 2 CTAs/SM ----------------
#define SSTR 72
#define SM_AH 0
#define SM_AL 9216                 // 64*72*2
#define SM_BH 18432
#define SM_BL 55296                // + 256*72*2
#define SM_GEMM_TOT 92160

__device__ __forceinline__ void mma16816(float* c, const uint32_t* a, const uint32_t* b) {
    asm volatile(
        "mma.sync.aligned.m16n8k16.row.col.f32.bf16.bf16.f32 "
        "{%0,%1,%2,%3}, {%4,%5,%6,%7}, {%8,%9}, {%0,%1,%2,%3};"
        : "+f"(c[0]), "+f"(c[1]), "+f"(c[2]), "+f"(c[3])
        : "r"(a[0]), "r"(a[1]), "r"(a[2]), "r"(a[3]), "r"(b[0]), "r"(b[1]));
}

__global__ __launch_bounds__(256, 2) void gemm_mma_kernel(
    const float* __restrict__ A, const float* __restrict__ attn_l,
    const float* __restrict__ attn_r, int Mtot)
{
    extern __shared__ char sm[];
    __nv_bfloat16* sAh = (__nv_bfloat16*)(sm + SM_AH);
    __nv_bfloat16* sAl = (__nv_bfloat16*)(sm + SM_AL);
    __nv_bfloat16* sBh = (__nv_bfloat16*)(sm + SM_BH);
    __nv_bfloat16* sBl = (__nv_bfloat16*)(sm + SM_BL);

    int tid = threadIdx.x, wid = tid >> 5, lane = tid & 31;
    int m0 = blockIdx.x * 64;
    int head = wid;              // warp covers cols head*32 .. +31, rows 0..63
    int fr = lane >> 2;
    int fk = (lane & 3) * 2;

    float acc[4][4][4];
    #pragma unroll
    for (int i = 0; i < 4; i++)
        #pragma unroll
        for (int j = 0; j < 4; j++)
            #pragma unroll
            for (int c = 0; c < 4; c++) acc[i][j][c] = 0.f;

    for (int kc = 0; kc < 4; kc++) {
        // --- A chunk: 64 rows x 64 k fp32 -> split bf16 hi/lo (1024 float4) ---
        #pragma unroll
        for (int g = tid; g < 1024; g += 256) {
            int row = g >> 4;
            int kq  = (g & 15) * 4;
            int grow = m0 + row;
            float4 v = make_float4(0.f, 0.f, 0.f, 0.f);
            if (grow < Mtot) v = *(const float4*)(A + (size_t)grow * FEATS + kc * 64 + kq);
            __nv_bfloat162 h01 = __floats2bfloat162_rn(v.x, v.y);
            __nv_bfloat162 h23 = __floats2bfloat162_rn(v.z, v.w);
            float lx = v.x - __bfloat162float(h01.x);
            float ly = v.y - __bfloat162float(h01.y);
            float lz = v.z - __bfloat162float(h23.x);
            float lw = v.w - __bfloat162float(h23.y);
            __nv_bfloat162 l01 = __floats2bfloat162_rn(lx, ly);
            __nv_bfloat162 l23 = __floats2bfloat162_rn(lz, lw);
            uint2 hp, lp;
            hp.x = reinterpret_cast<uint32_t&>(h01);
            hp.y = reinterpret_cast<uint32_t&>(h23);
            lp.x = reinterpret_cast<uint32_t&>(l01);
            lp.y = reinterpret_cast<uint32_t&>(l23);
            *(uint2*)(sAh + row * SSTR + kq) = hp;
            *(uint2*)(sAl + row * SSTR + kq) = lp;
        }
        // --- B chunk: 256 n-rows x 64 k bf16 hi/lo (2048 uint4) ---
        #pragma unroll
        for (int g = tid; g < 2048; g += 256) {
            int n  = g >> 3;
            int kq = (g & 7) * 8;
            *(uint4*)(sBh + n * SSTR + kq) = *(const uint4*)(g_Bhi + n * FEATS + kc * 64 + kq);
            *(uint4*)(sBl + n * SSTR + kq) = *(const uint4*)(g_Blo + n * FEATS + kc * 64 + kq);
        }
        __syncthreads();

        #pragma unroll
        for (int ks = 0; ks < 4; ks++) {
            int kb = ks * 16;
            uint32_t bh[4][2], bl[4][2];
            #pragma unroll
            for (int nt = 0; nt < 4; nt++) {
                int nn = head * 32 + nt * 8 + fr;
                bh[nt][0] = *(const uint32_t*)(sBh + nn * SSTR + kb + fk);
                bh[nt][1] = *(const uint32_t*)(sBh + nn * SSTR + kb + fk + 8);
                bl[nt][0] = *(const uint32_t*)(sBl + nn * SSTR + kb + fk);
                bl[nt][1] = *(const uint32_t*)(sBl + nn * SSTR + kb + fk + 8);
            }
            #pragma unroll
            for (int mt = 0; mt < 4; mt++) {
                int r0 = mt * 16 + fr;
                uint32_t ah[4], al[4];
                ah[0] = *(const uint32_t*)(sAh + r0 * SSTR + kb + fk);
                ah[1] = *(const uint32_t*)(sAh + (r0 + 8) * SSTR + kb + fk);
                ah[2] = *(const uint32_t*)(sAh + r0 * SSTR + kb + fk + 8);
                ah[3] = *(const uint32_t*)(sAh + (r0 + 8) * SSTR + kb + fk + 8);
                al[0] = *(const uint32_t*)(sAl + r0 * SSTR + kb + fk);
                al[1] = *(const uint32_t*)(sAl + (r0 + 8) * SSTR + kb + fk);
                al[2] = *(const uint32_t*)(sAl + r0 * SSTR + kb + fk + 8);
                al[3] = *(const uint32_t*)(sAl + (r0 + 8) * SSTR + kb + fk + 8);
                #pragma unroll
                for (int nt = 0; nt < 4; nt++) {
                    mma16816(acc[mt][nt], ah, bh[nt]);
                    mma16816(acc[mt][nt], ah, bl[nt]);
                    mma16816(acc[mt][nt], al, bh[nt]);
                }
            }
        }
        __syncthreads();
    }

    // --- epilogue: store h rows (fp16) + el/er (fp32, g_elr) ---
    float2 alv[4], arv[4];
    #pragma unroll
    for (int nt = 0; nt < 4; nt++) {
        alv[nt] = *(const float2*)(attn_l + head * 32 + nt * 8 + fk);
        arv[nt] = *(const float2*)(attn_r + head * 32 + nt * 8 + fk);
    }
    #pragma unroll
    for (int mt = 0; mt < 4; mt++) {
        #pragma unroll
        for (int half = 0; half < 2; half++) {
            int row = m0 + mt * 16 + fr + half * 8;
            int ci = half * 2;
            float el = 0.f, er = 0.f;
            if (row < Mtot) {
                __half* dp = g_hh + (size_t)row * FEATS + head * 32;
                #pragma unroll
                for (int nt = 0; nt < 4; nt++) {
                    float v0 = acc[mt][nt][ci], v1 = acc[mt][nt][ci + 1];
                    *(__half2*)(dp + nt * 8 + fk) = __floats2half2_rn(v0, v1);
                    el = fmaf(v0, alv[nt].x, fmaf(v1, alv[nt].y, el));
                    er = fmaf(v0, arv[nt].x, fmaf(v1, arv[nt].y, er));
                }
            }
            el += __shfl_xor_sync(~0u, el, 1);
            el += __shfl_xor_sync(~0u, el, 2);
            er += __shfl_xor_sync(~0u, er, 1);
            er += __shfl_xor_sync(~0u, er, 2);
            if ((lane & 3) == 0 && row < Mtot) {
                g_elr[row * 16 + head] = el;
                g_elr[row * 16 + 8 + head] = er;
            }
        }
    }
}

// ---------------- 2) zero degree ----------------
__global__ void zero_deg_kernel(int N) {
    int i = blockIdx.x * blockDim.x + threadIdx.x;
    if (i < N) g_deg[i] = 0;
}

// ---------------- 3) dst histogram ----------------
__global__ __launch_bounds__(256) void hist_kernel(const int* __restrict__ dst, int E) {
    int e = blockIdx.x * blockDim.x + threadIdx.x;
    if (e < E) atomicAdd(&g_deg[dst[e]], 1);
}

// ---------------- 4) single-block scan: deg -> off, cursor ----------------
__global__ __launch_bounds__(1024) void scan_kernel(int N) {
    __shared__ int wsum[32];
    __shared__ int s_carry;
    int tid = threadIdx.x, lane = tid & 31, w = tid >> 5;
    if (tid == 0) { s_carry = 0; g_off[0] = 0; }
    __syncthreads();

    for (int base = 0; base < N; base += 4096) {
        int i0 = base + tid * 4;
        int4 x = make_int4(0, 0, 0, 0);
        if (i0 + 3 < N) {
            x = *(const int4*)(g_deg + i0);
        } else {
            if (i0 < N)     x.x = g_deg[i0];
            if (i0 + 1 < N) x.y = g_deg[i0 + 1];
            if (i0 + 2 < N) x.z = g_deg[i0 + 2];
            if (i0 + 3 < N) x.w = g_deg[i0 + 3];
        }
        int p1 = x.x, p2 = p1 + x.y, p3 = p2 + x.z, p4 = p3 + x.w;
        int v = p4;
        #pragma unroll
        for (int o = 1; o < 32; o <<= 1) {
            int t = __shfl_up_sync(~0u, v, o);
            if (lane >= o) v += t;
        }
        if (lane == 31) wsum[w] = v;
        __syncthreads();
        if (w == 0) {
            int t = wsum[lane];
            #pragma unroll
            for (int o = 1; o < 32; o <<= 1) {
                int u = __shfl_up_sync(~0u, t, o);
                if (lane >= o) t += u;
            }
            wsum[lane] = t;
        }
        __syncthreads();
        int carry = s_carry;
        int base_t = carry + (w ? wsum[w - 1] : 0) + (v - p4);
        if (i0 < N)     { g_cursor[i0]     = base_t;      g_off[i0 + 1] = base_t + p1; }
        if (i0 + 1 < N) { g_cursor[i0 + 1] = base_t + p1; g_off[i0 + 2] = base_t + p2; }
        if (i0 + 2 < N) { g_cursor[i0 + 2] = base_t + p2; g_off[i0 + 3] = base_t + p3; }
        if (i0 + 3 < N) { g_cursor[i0 + 3] = base_t + p3; g_off[i0 + 4] = base_t + p4; }
        __syncthreads();
        if (tid == 0) s_carry = carry + wsum[31];
        __syncthreads();
    }
}

// ---------------- 5) ee-only pre-logits + CSR scatter (GEMM-INDEPENDENT) ----------------
__global__ __launch_bounds__(256) void edge_kernel(
    const float* __restrict__ edge_emb, const int* __restrict__ src,
    const int* __restrict__ dst, const float* __restrict__ W_e,
    const float* __restrict__ attn_e, int E)
{
    __shared__ float Msh[8][8];
    int tid = threadIdx.x;
    if (tid < 64) {
        int k = tid >> 3, hh = tid & 7;
        float s = 0.f;
        #pragma unroll
        for (int d = 0; d < DIM; d++)
            s += W_e[k * FEATS + hh * DIM + d] * attn_e[hh * DIM + d];
        Msh[k][hh] = s;
    }
    __syncthreads();

    int e0 = (blockIdx.x * 256 + tid) * 4;
    if (e0 >= E) return;
    int elim = min(e0 + 4, E);

    for (int e = e0; e < elim; e++) {
        int s_ = src[e], d_ = dst[e];
        float4 a0 = *(const float4*)(edge_emb + (size_t)e * 8);
        float4 a1 = *(const float4*)(edge_emb + (size_t)e * 8 + 4);
        float emb[8] = {a0.x, a0.y, a0.z, a0.w, a1.x, a1.y, a1.z, a1.w};
        float lg[8];
        #pragma unroll
        for (int hh = 0; hh < 8; hh++) {
            float ee = 0.f;
            #pragma unroll
            for (int k = 0; k < 8; k++) ee = fmaf(emb[k], Msh[k][hh], ee);
            lg[hh] = ee;
        }
        int pos = atomicAdd(&g_cursor[d_], 1);
        g_src_s[pos] = s_;
        *(float4*)(g_lgs + (size_t)pos * 8)     = make_float4(lg[0], lg[1], lg[2], lg[3]);
        *(float4*)(g_lgs + (size_t)pos * 8 + 4) = make_float4(lg[4], lg[5], lg[6], lg[7]);
    }
}

// ---------------- 6) single-pass softmax + aggregation ----------------
__global__ __launch_bounds__(256) void agg_kernel(
    const float* __restrict__ bias, float* __restrict__ out, int N)
{
    int warp = (blockIdx.x * blockDim.x + threadIdx.x) >> 5;
    int lane = threadIdx.x & 31;
    if (warp >= N) return;
    int beg = g_off[warp], end = g_off[warp + 1];

    int hh2 = lane >> 2;
    int col = lane * 8;
    float er2 = g_elr[warp * 16 + 8 + hh2];

    float S = 0.f;
    float4 acc0 = make_float4(0.f, 0.f, 0.f, 0.f);
    float4 acc1 = make_float4(0.f, 0.f, 0.f, 0.f);

    int j = beg;
    for (; j + 3 < end; j += 4) {
        int s[4];
        #pragma unroll
        for (int q = 0; q < 4; q++) s[q] = g_src_s[j + q];
        float xr[4];
        #pragma unroll
        for (int q = 0; q < 4; q++) xr[q] = g_lgs[(size_t)(j + q) * 8 + hh2];
        float elq[4];
        #pragma unroll
        for (int q = 0; q < 4; q++) elq[q] = g_elr[(size_t)s[q] * 16 + hh2];
        uint4 hq[4];
        #pragma unroll
        for (int q = 0; q < 4; q++)
            hq[q] = *(const uint4*)(g_hh + (size_t)s[q] * FEATS + col);

        #pragma unroll
        for (int q = 0; q < 4; q++) {
            float x = xr[q] + elq[q] + er2;
            x = x >= 0.f ? x : 0.2f * x;
            float w = __expf(x);
            S += w;
            float2 f0 = __half22float2(*reinterpret_cast<__half2*>(&hq[q].x));
            float2 f1 = __half22float2(*reinterpret_cast<__half2*>(&hq[q].y));
            float2 f2 = __half22float2(*reinterpret_cast<__half2*>(&hq[q].z));
            float2 f3 = __half22float2(*reinterpret_cast<__half2*>(&hq[q].w));
            acc0.x = fmaf(w, f0.x, acc0.x);
            acc0.y = fmaf(w, f0.y, acc0.y);
            acc0.z = fmaf(w, f1.x, acc0.z);
            acc0.w = fmaf(w, f1.y, acc0.w);
            acc1.x = fmaf(w, f2.x, acc1.x);
            acc1.y = fmaf(w, f2.y, acc1.y);
            acc1.z = fmaf(w, f3.x, acc1.z);
            acc1.w = fmaf(w, f3.y, acc1.w);
        }
    }
    for (; j < end; j++) {
        int sidx = g_src_s[j];
        float x = g_lgs[(size_t)j * 8 + hh2] + g_elr[(size_t)sidx * 16 + hh2] + er2;
        x = x >= 0.f ? x : 0.2f * x;
        float w = __expf(x);
        S += w;
        uint4 q = *(const uint4*)(g_hh + (size_t)sidx * FEATS + col);
        float2 f0 = __half22float2(*reinterpret_cast<__half2*>(&q.x));
        float2 f1 = __half22float2(*reinterpret_cast<__half2*>(&q.y));
        float2 f2 = __half22float2(*reinterpret_cast<__half2*>(&q.z));
        float2 f3 = __half22float2(*reinterpret_cast<__half2*>(&q.w));
        acc0.x = fmaf(w, f0.x, acc0.x);
        acc0.y = fmaf(w, f0.y, acc0.y);
        acc0.z = fmaf(w, f1.x, acc0.z);
        acc0.w = fmaf(w, f1.y, acc0.w);
        acc1.x = fmaf(w, f2.x, acc1.x);
        acc1.y = fmaf(w, f2.y, acc1.y);
        acc1.z = fmaf(w, f3.x, acc1.z);
        acc1.w = fmaf(w, f3.y, acc1.w);
    }

    float inv = 1.0f / (S + 1e-9f);
    const float4* bp = (const float4*)(bias + col);
    float4 b0 = bp[0], b1 = bp[1];
    float4* op = (float4*)(out + (size_t)warp * FEATS + col);
    op[0] = make_float4(fmaf(acc0.x, inv, b0.x), fmaf(acc0.y, inv, b0.y),
                        fmaf(acc0.z, inv, b0.z), fmaf(acc0.w, inv, b0.w));
    op[1] = make_float4(fmaf(acc1.x, inv, b1.x), fmaf(acc1.y, inv, b1.y),
                        fmaf(acc1.z, inv, b1.z), fmaf(acc1.w, inv, b1.w));
}

// ---------------- launch: 2-branch DAG; gemm as 4th launch for ncu capture ----------------
extern "C" void kernel_launch(void* const* d_in, const int* in_sizes, int n_in,
                              void* d_out, int out_size)
{
    const float* feat     = (const float*)d_in[0];
    const float* edge_emb = (const float*)d_in[1];
    const int*   src      = (const int*)d_in[2];
    const int*   dst      = (const int*)d_in[3];
    const float* W_src    = (const float*)d_in[4];
    const float* W_e      = (const float*)d_in[5];
    const float* attn_l   = (const float*)d_in[6];
    const float* attn_r   = (const float*)d_in[7];
    const float* attn_e   = (const float*)d_in[8];
    const float* bias     = (const float*)d_in[9];
    float* out = (float*)d_out;

    int N = in_sizes[0] / FEATS;   // 50000
    int E = in_sizes[2];           // 800000

    cudaFuncSetAttribute(gemm_mma_kernel,
                         cudaFuncAttributeMaxDynamicSharedMemorySize, SM_GEMM_TOT);

    // Side stream for CSR build + ee pre-logits (independent of GEMM chain).
    // Streams/events intentionally not destroyed during capture (bounded host leak).
    cudaStream_t s2;
    cudaStreamCreateWithFlags(&s2, cudaStreamNonBlocking);
    cudaEvent_t evFork, evJoin;
    cudaEventCreateWithFlags(&evFork, cudaEventDisableTiming);
    cudaEventCreateWithFlags(&evJoin, cudaEventDisableTiming);

    cudaEventRecord(evFork, 0);
    cudaStreamWaitEvent(s2, evFork, 0);

    // submission order keeps gemm as the 4th launch (ncu capture slot):
    zero_deg_kernel<<<(N + 255) / 256, 256, 0, s2>>>(N);                 // 1
    hist_kernel<<<(E + 255) / 256, 256, 0, s2>>>(dst, E);                // 2
    prep_w_kernel<<<FEATS, FEATS>>>(W_src);                              // 3 (main)
    int gtiles = (N + 63) / 64;
    gemm_mma_kernel<<<gtiles, 256, SM_GEMM_TOT>>>(feat, attn_l, attn_r, N); // 4 (main) <- ncu
    scan_kernel<<<1, 1024, 0, s2>>>(N);                                  // 5
    edge_kernel<<<((E + 3) / 4 + 255) / 256, 256, 0, s2>>>(edge_emb, src, dst, W_e, attn_e, E); // 6

    cudaEventRecord(evJoin, s2);
    cudaStreamWaitEvent(0, evJoin, 0);

    // join: aggregate (needs h/el/er from GEMM and CSR+lgs from side stream)
    agg_kernel<<<((N * 32) + 255) / 256, 256>>>(bias, out, N);           // 7
}

// round 16
// speedup vs baseline: 1.2222x; 1.0296x over previous
#include <cuda_runtime.h>
#include <cuda_bf16.h>
#include <cuda_fp16.h>
#include <math.h>
#include <cstdint>

#define HEADS 8
#define DIM 32
#define FEATS 256
#define NNODE_MAX 50000
#define NEDGE_MAX 800000

// ---------------- device scratch (no allocs allowed) ----------------
__device__ __half g_hh[(size_t)NNODE_MAX * FEATS];    // projected node features (fp16, 512B rows)
__device__ float g_elr[NNODE_MAX * 16];               // [node][0..7]=el, [8..15]=er
__device__ float g_lgs[(size_t)NEDGE_MAX * 8];        // ee-only pre-logits in CSR order
__device__ int   g_src_s[NEDGE_MAX];                  // src in CSR order
__device__ int   g_deg[NNODE_MAX];
__device__ int   g_off[NNODE_MAX + 1];
__device__ int   g_cursor[NNODE_MAX];
__device__ __nv_bfloat16 g_Bhi[FEATS * FEATS];        // W^T hi split, [n][k]
__device__ __nv_bfloat16 g_Blo[FEATS * FEATS];        // W^T lo split, [n][k]

// ---------------- 0) prep: W^T split into bf16 hi/lo ----------------
__global__ void prep_w_kernel(const float* __restrict__ W) {
    int k = blockIdx.x;          // 0..255
    int n = threadIdx.x;         // 0..255
    float v = W[k * FEATS + n];
    __nv_bfloat16 hi = __float2bfloat16(v);
    float lo = v - __bfloat162float(hi);
    g_Bhi[n * FEATS + k] = hi;
    g_Blo[n * FEATS + k] = __float2bfloat16(lo);
}

// ---------------- 1) bf16 split-3 HMMA GEMM, M64xN256 tiles, ldmatrix frags ----------------
#define SSTR 72
#define SM_AH 0
#define SM_AL 9216                 // 64*72*2
#define SM_BH 18432
#define SM_BL 55296                // + 256*72*2
#define SM_GEMM_TOT 92160

__device__ __forceinline__ void mma16816(float* c, const uint32_t* a, const uint32_t* b) {
    asm volatile(
        "mma.sync.aligned.m16n8k16.row.col.f32.bf16.bf16.f32 "
        "{%0,%1,%2,%3}, {%4,%5,%6,%7}, {%8,%9}, {%0,%1,%2,%3};"
        : "+f"(c[0]), "+f"(c[1]), "+f"(c[2]), "+f"(c[3])
        : "r"(a[0]), "r"(a[1]), "r"(a[2]), "r"(a[3]), "r"(b[0]), "r"(b[1]));
}

__device__ __forceinline__ void ldsm_x4(uint32_t* r, const __nv_bfloat16* p) {
    uint32_t a = (uint32_t)__cvta_generic_to_shared(p);
    asm volatile("ldmatrix.sync.aligned.m8n8.x4.shared.b16 {%0,%1,%2,%3}, [%4];"
        : "=r"(r[0]), "=r"(r[1]), "=r"(r[2]), "=r"(r[3]) : "r"(a));
}

__global__ __launch_bounds__(256, 2) void gemm_mma_kernel(
    const float* __restrict__ A, const float* __restrict__ attn_l,
    const float* __restrict__ attn_r, int Mtot)
{
    extern __shared__ char sm[];
    __nv_bfloat16* sAh = (__nv_bfloat16*)(sm + SM_AH);
    __nv_bfloat16* sAl = (__nv_bfloat16*)(sm + SM_AL);
    __nv_bfloat16* sBh = (__nv_bfloat16*)(sm + SM_BH);
    __nv_bfloat16* sBl = (__nv_bfloat16*)(sm + SM_BL);

    int tid = threadIdx.x, wid = tid >> 5, lane = tid & 31;
    int m0 = blockIdx.x * 64;
    int head = wid;              // warp covers cols head*32 .. +31, rows 0..63
    int fr = lane >> 2;
    int fk = (lane & 3) * 2;
    int ltile = lane >> 3;       // ldmatrix lane group 0..3
    int lrow  = lane & 7;        // row within ldmatrix 8x8 tile

    float acc[4][4][4];
    #pragma unroll
    for (int i = 0; i < 4; i++)
        #pragma unroll
        for (int j = 0; j < 4; j++)
            #pragma unroll
            for (int c = 0; c < 4; c++) acc[i][j][c] = 0.f;

    // phase-stagger co-resident CTAs: odd CTAs rotate the kc order
    int kc_rot = (blockIdx.x & 1) * 2;

    for (int kci = 0; kci < 4; kci++) {
        int kc = (kci + kc_rot) & 3;
        // --- A chunk: 64 rows x 64 k fp32 -> split bf16 hi/lo (1024 float4) ---
        #pragma unroll
        for (int g = tid; g < 1024; g += 256) {
            int row = g >> 4;
            int kq  = (g & 15) * 4;
            int grow = m0 + row;
            float4 v = make_float4(0.f, 0.f, 0.f, 0.f);
            if (grow < Mtot) v = *(const float4*)(A + (size_t)grow * FEATS + kc * 64 + kq);
            __nv_bfloat162 h01 = __floats2bfloat162_rn(v.x, v.y);
            __nv_bfloat162 h23 = __floats2bfloat162_rn(v.z, v.w);
            float lx = v.x - __bfloat162float(h01.x);
            float ly = v.y - __bfloat162float(h01.y);
            float lz = v.z - __bfloat162float(h23.x);
            float lw = v.w - __bfloat162float(h23.y);
            __nv_bfloat162 l01 = __floats2bfloat162_rn(lx, ly);
            __nv_bfloat162 l23 = __floats2bfloat162_rn(lz, lw);
            uint2 hp, lp;
            hp.x = reinterpret_cast<uint32_t&>(h01);
            hp.y = reinterpret_cast<uint32_t&>(h23);
            lp.x = reinterpret_cast<uint32_t&>(l01);
            lp.y = reinterpret_cast<uint32_t&>(l23);
            *(uint2*)(sAh + row * SSTR + kq) = hp;
            *(uint2*)(sAl + row * SSTR + kq) = lp;
        }
        // --- B chunk: 256 n-rows x 64 k bf16 hi/lo (2048 uint4) ---
        #pragma unroll
        for (int g = tid; g < 2048; g += 256) {
            int n  = g >> 3;
            int kq = (g & 7) * 8;
            *(uint4*)(sBh + n * SSTR + kq) = *(const uint4*)(g_Bhi + n * FEATS + kc * 64 + kq);
            *(uint4*)(sBl + n * SSTR + kq) = *(const uint4*)(g_Blo + n * FEATS + kc * 64 + kq);
        }
        __syncthreads();

        #pragma unroll
        for (int ks = 0; ks < 4; ks++) {
            int kb = ks * 16;
            // --- B fragments via ldmatrix: tiles (n, klo),(n, khi),(n+8, klo),(n+8, khi) ---
            uint32_t bh[4][2], bl[4][2];
            #pragma unroll
            for (int ntp = 0; ntp < 2; ntp++) {
                const int nrow = head * 32 + ntp * 16 + ((ltile >> 1) * 8) + lrow;
                const int kcol = kb + (ltile & 1) * 8;
                uint32_t r[4];
                ldsm_x4(r, sBh + nrow * SSTR + kcol);
                bh[ntp * 2][0] = r[0]; bh[ntp * 2][1] = r[1];
                bh[ntp * 2 + 1][0] = r[2]; bh[ntp * 2 + 1][1] = r[3];
                ldsm_x4(r, sBl + nrow * SSTR + kcol);
                bl[ntp * 2][0] = r[0]; bl[ntp * 2][1] = r[1];
                bl[ntp * 2 + 1][0] = r[2]; bl[ntp * 2 + 1][1] = r[3];
            }
            #pragma unroll
            for (int mt = 0; mt < 4; mt++) {
                const int arow = mt * 16 + ((ltile & 1) * 8) + lrow;
                const int kcol = kb + (ltile >> 1) * 8;
                uint32_t ah[4], al[4];
                ldsm_x4(ah, sAh + arow * SSTR + kcol);
                ldsm_x4(al, sAl + arow * SSTR + kcol);
                #pragma unroll
                for (int nt = 0; nt < 4; nt++) {
                    mma16816(acc[mt][nt], ah, bh[nt]);
                    mma16816(acc[mt][nt], ah, bl[nt]);
                    mma16816(acc[mt][nt], al, bh[nt]);
                }
            }
        }
        __syncthreads();
    }

    // --- epilogue: store h rows (fp16) + el/er (fp32, g_elr) ---
    float2 alv[4], arv[4];
    #pragma unroll
    for (int nt = 0; nt < 4; nt++) {
        alv[nt] = *(const float2*)(attn_l + head * 32 + nt * 8 + fk);
        arv[nt] = *(const float2*)(attn_r + head * 32 + nt * 8 + fk);
    }
    #pragma unroll
    for (int mt = 0; mt < 4; mt++) {
        #pragma unroll
        for (int half = 0; half < 2; half++) {
            int row = m0 + mt * 16 + fr + half * 8;
            int ci = half * 2;
            float el = 0.f, er = 0.f;
            if (row < Mtot) {
                __half* dp = g_hh + (size_t)row * FEATS + head * 32;
                #pragma unroll
                for (int nt = 0; nt < 4; nt++) {
                    float v0 = acc[mt][nt][ci], v1 = acc[mt][nt][ci + 1];
                    *(__half2*)(dp + nt * 8 + fk) = __floats2half2_rn(v0, v1);
                    el = fmaf(v0, alv[nt].x, fmaf(v1, alv[nt].y, el));
                    er = fmaf(v0, arv[nt].x, fmaf(v1, arv[nt].y, er));
                }
            }
            el += __shfl_xor_sync(~0u, el, 1);
            el += __shfl_xor_sync(~0u, el, 2);
            er += __shfl_xor_sync(~0u, er, 1);
            er += __shfl_xor_sync(~0u, er, 2);
            if ((lane & 3) == 0 && row < Mtot) {
                g_elr[row * 16 + head] = el;
                g_elr[row * 16 + 8 + head] = er;
            }
        }
    }
}

// ---------------- 2) zero degree ----------------
__global__ void zero_deg_kernel(int N) {
    int i = blockIdx.x * blockDim.x + threadIdx.x;
    if (i < N) g_deg[i] = 0;
}

// ---------------- 3) dst histogram ----------------
__global__ __launch_bounds__(256) void hist_kernel(const int* __restrict__ dst, int E) {
    int e = blockIdx.x * blockDim.x + threadIdx.x;
    if (e < E) atomicAdd(&g_deg[dst[e]], 1);
}

// ---------------- 4) single-block scan: deg -> off, cursor ----------------
__global__ __launch_bounds__(1024) void scan_kernel(int N) {
    __shared__ int wsum[32];
    __shared__ int s_carry;
    int tid = threadIdx.x, lane = tid & 31, w = tid >> 5;
    if (tid == 0) { s_carry = 0; g_off[0] = 0; }
    __syncthreads();

    for (int base = 0; base < N; base += 4096) {
        int i0 = base + tid * 4;
        int4 x = make_int4(0, 0, 0, 0);
        if (i0 + 3 < N) {
            x = *(const int4*)(g_deg + i0);
        } else {
            if (i0 < N)     x.x = g_deg[i0];
            if (i0 + 1 < N) x.y = g_deg[i0 + 1];
            if (i0 + 2 < N) x.z = g_deg[i0 + 2];
            if (i0 + 3 < N) x.w = g_deg[i0 + 3];
        }
        int p1 = x.x, p2 = p1 + x.y, p3 = p2 + x.z, p4 = p3 + x.w;
        int v = p4;
        #pragma unroll
        for (int o = 1; o < 32; o <<= 1) {
            int t = __shfl_up_sync(~0u, v, o);
            if (lane >= o) v += t;
        }
        if (lane == 31) wsum[w] = v;
        __syncthreads();
        if (w == 0) {
            int t = wsum[lane];
            #pragma unroll
            for (int o = 1; o < 32; o <<= 1) {
                int u = __shfl_up_sync(~0u, t, o);
                if (lane >= o) t += u;
            }
            wsum[lane] = t;
        }
        __syncthreads();
        int carry = s_carry;
        int base_t = carry + (w ? wsum[w - 1] : 0) + (v - p4);
        if (i0 < N)     { g_cursor[i0]     = base_t;      g_off[i0 + 1] = base_t + p1; }
        if (i0 + 1 < N) { g_cursor[i0 + 1] = base_t + p1; g_off[i0 + 2] = base_t + p2; }
        if (i0 + 2 < N) { g_cursor[i0 + 2] = base_t + p2; g_off[i0 + 3] = base_t + p3; }
        if (i0 + 3 < N) { g_cursor[i0 + 3] = base_t + p3; g_off[i0 + 4] = base_t + p4; }
        __syncthreads();
        if (tid == 0) s_carry = carry + wsum[31];
        __syncthreads();
    }
}

// ---------------- 5) ee-only pre-logits + CSR scatter (GEMM-INDEPENDENT) ----------------
__global__ __launch_bounds__(256) void edge_kernel(
    const float* __restrict__ edge_emb, const int* __restrict__ src,
    const int* __restrict__ dst, const float* __restrict__ W_e,
    const float* __restrict__ attn_e, int E)
{
    __shared__ float Msh[8][8];
    int tid = threadIdx.x;
    if (tid < 64) {
        int k = tid >> 3, hh = tid & 7;
        float s = 0.f;
        #pragma unroll
        for (int d = 0; d < DIM; d++)
            s += W_e[k * FEATS + hh * DIM + d] * attn_e[hh * DIM + d];
        Msh[k][hh] = s;
    }
    __syncthreads();

    int e0 = (blockIdx.x * 256 + tid) * 4;
    if (e0 >= E) return;
    int elim = min(e0 + 4, E);

    for (int e = e0; e < elim; e++) {
        int s_ = src[e], d_ = dst[e];
        float4 a0 = *(const float4*)(edge_emb + (size_t)e * 8);
        float4 a1 = *(const float4*)(edge_emb + (size_t)e * 8 + 4);
        float emb[8] = {a0.x, a0.y, a0.z, a0.w, a1.x, a1.y, a1.z, a1.w};
        float lg[8];
        #pragma unroll
        for (int hh = 0; hh < 8; hh++) {
            float ee = 0.f;
            #pragma unroll
            for (int k = 0; k < 8; k++) ee = fmaf(emb[k], Msh[k][hh], ee);
            lg[hh] = ee;
        }
        int pos = atomicAdd(&g_cursor[d_], 1);
        g_src_s[pos] = s_;
        *(float4*)(g_lgs + (size_t)pos * 8)     = make_float4(lg[0], lg[1], lg[2], lg[3]);
        *(float4*)(g_lgs + (size_t)pos * 8 + 4) = make_float4(lg[4], lg[5], lg[6], lg[7]);
    }
}

// ---------------- 6) single-pass softmax + aggregation ----------------
__global__ __launch_bounds__(256) void agg_kernel(
    const float* __restrict__ bias, float* __restrict__ out, int N)
{
    int warp = (blockIdx.x * blockDim.x + threadIdx.x) >> 5;
    int lane = threadIdx.x & 31;
    if (warp >= N) return;
    int beg = g_off[warp], end = g_off[warp + 1];

    int hh2 = lane >> 2;
    int col = lane * 8;
    float er2 = g_elr[warp * 16 + 8 + hh2];

    float S = 0.f;
    float4 acc0 = make_float4(0.f, 0.f, 0.f, 0.f);
    float4 acc1 = make_float4(0.f, 0.f, 0.f, 0.f);

    int j = beg;
    for (; j + 3 < end; j += 4) {
        int s[4];
        #pragma unroll
        for (int q = 0; q < 4; q++) s[q] = g_src_s[j + q];
        float xr[4];
        #pragma unroll
        for (int q = 0; q < 4; q++) xr[q] = g_lgs[(size_t)(j + q) * 8 + hh2];
        float elq[4];
        #pragma unroll
        for (int q = 0; q < 4; q++) elq[q] = g_elr[(size_t)s[q] * 16 + hh2];
        uint4 hq[4];
        #pragma unroll
        for (int q = 0; q < 4; q++)
            hq[q] = *(const uint4*)(g_hh + (size_t)s[q] * FEATS + col);

        #pragma unroll
        for (int q = 0; q < 4; q++) {
            float x = xr[q] + elq[q] + er2;
            x = x >= 0.f ? x : 0.2f * x;
            float w = __expf(x);
            S += w;
            float2 f0 = __half22float2(*reinterpret_cast<__half2*>(&hq[q].x));
            float2 f1 = __half22float2(*reinterpret_cast<__half2*>(&hq[q].y));
            float2 f2 = __half22float2(*reinterpret_cast<__half2*>(&hq[q].z));
            float2 f3 = __half22float2(*reinterpret_cast<__half2*>(&hq[q].w));
            acc0.x = fmaf(w, f0.x, acc0.x);
            acc0.y = fmaf(w, f0.y, acc0.y);
            acc0.z = fmaf(w, f1.x, acc0.z);
            acc0.w = fmaf(w, f1.y, acc0.w);
            acc1.x = fmaf(w, f2.x, acc1.x);
            acc1.y = fmaf(w, f2.y, acc1.y);
            acc1.z = fmaf(w, f3.x, acc1.z);
            acc1.w = fmaf(w, f3.y, acc1.w);
        }
    }
    for (; j < end; j++) {
        int sidx = g_src_s[j];
        float x = g_lgs[(size_t)j * 8 + hh2] + g_elr[(size_t)sidx * 16 + hh2] + er2;
        x = x >= 0.f ? x : 0.2f * x;
        float w = __expf(x);
        S += w;
        uint4 q = *(const uint4*)(g_hh + (size_t)sidx * FEATS + col);
        float2 f0 = __half22float2(*reinterpret_cast<__half2*>(&q.x));
        float2 f1 = __half22float2(*reinterpret_cast<__half2*>(&q.y));
        float2 f2 = __half22float2(*reinterpret_cast<__half2*>(&q.z));
        float2 f3 = __half22float2(*reinterpret_cast<__half2*>(&q.w));
        acc0.x = fmaf(w, f0.x, acc0.x);
        acc0.y = fmaf(w, f0.y, acc0.y);
        acc0.z = fmaf(w, f1.x, acc0.z);
        acc0.w = fmaf(w, f1.y, acc0.w);
        acc1.x = fmaf(w, f2.x, acc1.x);
        acc1.y = fmaf(w, f2.y, acc1.y);
        acc1.z = fmaf(w, f3.x, acc1.z);
        acc1.w = fmaf(w, f3.y, acc1.w);
    }

    float inv = 1.0f / (S + 1e-9f);
    const float4* bp = (const float4*)(bias + col);
    float4 b0 = bp[0], b1 = bp[1];
    float4* op = (float4*)(out + (size_t)warp * FEATS + col);
    op[0] = make_float4(fmaf(acc0.x, inv, b0.x), fmaf(acc0.y, inv, b0.y),
                        fmaf(acc0.z, inv, b0.z), fmaf(acc0.w, inv, b0.w));
    op[1] = make_float4(fmaf(acc1.x, inv, b1.x), fmaf(acc1.y, inv, b1.y),
                        fmaf(acc1.z, inv, b1.z), fmaf(acc1.w, inv, b1.w));
}

// ---------------- launch: 2-branch DAG; gemm as 4th launch for ncu capture ----------------
extern "C" void kernel_launch(void* const* d_in, const int* in_sizes, int n_in,
                              void* d_out, int out_size)
{
    const float* feat     = (const float*)d_in[0];
    const float* edge_emb = (const float*)d_in[1];
    const int*   src      = (const int*)d_in[2];
    const int*   dst      = (const int*)d_in[3];
    const float* W_src    = (const float*)d_in[4];
    const float* W_e      = (const float*)d_in[5];
    const float* attn_l   = (const float*)d_in[6];
    const float* attn_r   = (const float*)d_in[7];
    const float* attn_e   = (const float*)d_in[8];
    const float* bias     = (const float*)d_in[9];
    float* out = (float*)d_out;

    int N = in_sizes[0] / FEATS;   // 50000
    int E = in_sizes[2];           // 800000

    cudaFuncSetAttribute(gemm_mma_kernel,
                         cudaFuncAttributeMaxDynamicSharedMemorySize, SM_GEMM_TOT);

    // Side stream for CSR build + ee pre-logits (independent of GEMM chain).
    // Streams/events intentionally not destroyed during capture (bounded host leak).
    cudaStream_t s2;
    cudaStreamCreateWithFlags(&s2, cudaStreamNonBlocking);
    cudaEvent_t evFork, evJoin;
    cudaEventCreateWithFlags(&evFork, cudaEventDisableTiming);
    cudaEventCreateWithFlags(&evJoin, cudaEventDisableTiming);

    cudaEventRecord(evFork, 0);
    cudaStreamWaitEvent(s2, evFork, 0);

    // submission order keeps gemm as the 4th launch (ncu capture slot):
    zero_deg_kernel<<<(N + 255) / 256, 256, 0, s2>>>(N);                 // 1
    hist_kernel<<<(E + 255) / 256, 256, 0, s2>>>(dst, E);                // 2
    prep_w_kernel<<<FEATS, FEATS>>>(W_src);                              // 3 (main)
    int gtiles = (N + 63) / 64;
    gemm_mma_kernel<<<gtiles, 256, SM_GEMM_TOT>>>(feat, attn_l, attn_r, N); // 4 (main) <- ncu
    scan_kernel<<<1, 1024, 0, s2>>>(N);                                  // 5
    edge_kernel<<<((E + 3) / 4 + 255) / 256, 256, 0, s2>>>(edge_emb, src, dst, W_e, attn_e, E); // 6

    cudaEventRecord(evJoin, s2);
    cudaStreamWaitEvent(0, evJoin, 0);

    // join: aggregate (needs h/el/er from GEMM and CSR+lgs from side stream)
    agg_kernel<<<((N * 32) + 255) / 256, 256>>>(bias, out, N);           // 7
}